// round 3
// baseline (speedup 1.0000x reference)
#include <cuda_runtime.h>
#include <cstdint>

// ---------------------------------------------------------------------------
// GRU acoustic model:
//   encoder GRU(13 -> 300) over T=2048 (only final h needed),
//   emb = relu(h_last @ fc_W^T + fc_b),
//   decoder GRU(300 -> 13), constant input emb, T=2048 (all h emitted).
//
// Encoder: 16 clusters x 8 CTAs, 512 thr. Cluster = 4 batches. Each CTA holds
// a 38-hidden-unit slice of Whh (3 gates) TRANSPOSED in smem (Wt[k][row]).
// Per step: partial dots (k split into quarters per thread), smem reduce +
// on-the-fly gi, gates, DSMEM broadcast of the new h slice to all 8 peers,
// one barrier.cluster per step.
//
// Decoder (fused with fc): 64 CTAs (one per batch), warp-synchronous loop,
// dec_Whh held in registers.
// ---------------------------------------------------------------------------

#define KB   64
#define KT   2048
#define KF   13
#define KH   300
#define KCL  8      // CTAs per cluster
#define KBPC 4      // batches per cluster
#define KU   38     // hidden units per CTA (rank 7 uses 34)
#define KROWS 114   // 3 * KU gate rows per CTA
#define KRPAD 128
#define KTHR 512

struct EncSmem {
    float Wt[KH * KRPAD];        // [k][row], row = g*38 + jl      (153600 B)
    float h[2][KH][KBPC];        // double-buffered hidden, [k][batch]
    float part[KRPAD][4][KBPC];  // partial sums [row][quarter][batch]
    float A[KRPAD][KBPC];        // pre-activations (r,z full; n: gh_n + bhh_n)
    float Bn[40][KBPC];          // n rows: gi_n + bih_n
    float WihT[16][KRPAD];       // input weights transposed [f][row]
    float bihS[KRPAD];
    float bhhS[KRPAD];
    float xs[2][KBPC][16];       // double-buffered x_t per batch
};
static_assert(sizeof(EncSmem) <= 232448, "smem too big");

__device__ float g_henc[KB * KH];

__device__ __forceinline__ float sigm(float v) {
    return 1.0f / (1.0f + expf(-v));
}
__device__ __forceinline__ void cluster_sync() {
    asm volatile("barrier.cluster.arrive.aligned;\n\t"
                 "barrier.cluster.wait.aligned;" ::: "memory");
}
__device__ __forceinline__ uint32_t smem_u32(const void* p) {
    uint32_t a;
    asm("{ .reg .u64 t; cvta.to.shared.u64 t, %1; cvt.u32.u64 %0, t; }"
        : "=r"(a) : "l"(p));
    return a;
}
__device__ __forceinline__ void dsmem_store_f32(uint32_t laddr, uint32_t rank, float v) {
    uint32_t ra;
    asm volatile("mapa.shared::cluster.u32 %0, %1, %2;"
                 : "=r"(ra) : "r"(laddr), "r"(rank));
    asm volatile("st.shared::cluster.f32 [%0], %1;" :: "r"(ra), "f"(v) : "memory");
}

extern __shared__ __align__(16) float enc_sm_raw[];

__global__ void __cluster_dims__(KCL, 1, 1) __launch_bounds__(KTHR, 1)
enc_kernel(const float* __restrict__ x,   const float* __restrict__ Wih,
           const float* __restrict__ Whh, const float* __restrict__ bih,
           const float* __restrict__ bhh)
{
    EncSmem* S = reinterpret_cast<EncSmem*>(enc_sm_raw);
    const int tid     = threadIdx.x;
    const int cluster = blockIdx.x / KCL;
    const int rank    = blockIdx.x % KCL;
    const int u0      = rank * KU;
    const int ucnt    = (KH - u0 < KU) ? (KH - u0) : KU;

    // ---- init: zero everything that is read, then fill weight slices ----
    for (int i = tid; i < KH * KRPAD; i += KTHR) S->Wt[i] = 0.f;
    for (int i = tid; i < 2 * KH * KBPC; i += KTHR) (&S->h[0][0][0])[i] = 0.f;
    for (int i = tid; i < 16 * KRPAD; i += KTHR) (&S->WihT[0][0])[i] = 0.f;
    for (int i = tid; i < KRPAD; i += KTHR) { S->bihS[i] = 0.f; S->bhhS[i] = 0.f; }
    __syncthreads();

    for (int i = tid; i < 3 * ucnt * KH; i += KTHR) {
        const int k  = i % KH;
        const int rr = i / KH;
        const int g = rr / ucnt, jl = rr % ucnt;
        S->Wt[k * KRPAD + g * KU + jl] = Whh[(size_t)(g * KH + u0 + jl) * KH + k];
    }
    for (int i = tid; i < 3 * ucnt * KF; i += KTHR) {
        const int f  = i % KF;
        const int rr = i / KF;
        const int g = rr / ucnt, jl = rr % ucnt;
        S->WihT[f][g * KU + jl] = Wih[(size_t)(g * KH + u0 + jl) * KF + f];
    }
    if (tid < KROWS) {
        const int g = tid / KU, jl = tid % KU;
        if (jl < ucnt) {
            S->bihS[tid] = bih[g * KH + u0 + jl];
            S->bhhS[tid] = bhh[g * KH + u0 + jl];
        }
    }
    if (tid < KBPC * KF) {
        const int m = tid / KF, f = tid % KF;
        S->xs[0][m][f] = x[((size_t)(cluster * KBPC + m) * KT + 0) * KF + f];
    }
    __syncthreads();
    cluster_sync();   // all peers initialized before any remote store / read

    int p = 0;
    const int q   = tid >> 7;     // k-quarter (uniform per warp)
    const int row = tid & 127;    // gate row  (consecutive lanes -> coalesced)

    for (int t = 0; t < KT; ++t) {
        // prefetch next step's x into registers (LDG overlaps stage 1)
        float xv = 0.f; int pm = 0, pf = 0;
        const bool doPref = (tid < KBPC * KF) && (t + 1 < KT);
        if (doPref) {
            pm = tid / KF; pf = tid % KF;
            xv = x[((size_t)(cluster * KBPC + pm) * KT + (t + 1)) * KF + pf];
        }

        // ---- stage 1: partial gh = Whh_slice . h over this thread's quarter
        {
            float a0 = 0.f, a1 = 0.f, a2 = 0.f, a3 = 0.f;
            const float*  wbase = &S->Wt[row];
            const float4* hq    = reinterpret_cast<const float4*>(&S->h[p][0][0]);
            const int k0 = q * 75;
            #pragma unroll 15
            for (int i = 0; i < 75; ++i) {
                const int k = k0 + i;
                const float  w  = wbase[(size_t)k * KRPAD]; // coalesced 128B
                const float4 hv = hq[k];                    // broadcast
                a0 = fmaf(w, hv.x, a0);
                a1 = fmaf(w, hv.y, a1);
                a2 = fmaf(w, hv.z, a2);
                a3 = fmaf(w, hv.w, a3);
            }
            *reinterpret_cast<float4*>(&S->part[row][q][0]) =
                make_float4(a0, a1, a2, a3);
        }
        __syncthreads();

        // ---- stage 2: reduce quarters, add gi = x.Wih^T and biases ----
        if (tid < KROWS * KBPC) {
            const int r2 = tid >> 2, m = tid & 3;
            float tot = S->part[r2][0][m] + S->part[r2][1][m]
                      + S->part[r2][2][m] + S->part[r2][3][m];
            const float* xr = S->xs[t & 1][m];
            float gi = 0.f;
            #pragma unroll
            for (int f = 0; f < KF; ++f) gi = fmaf(S->WihT[f][r2], xr[f], gi);
            if (r2 < 2 * KU) {                      // r and z gates: full preact
                S->A[r2][m] = tot + gi + S->bihS[r2] + S->bhhS[r2];
            } else {                                // n gate: keep halves apart
                S->A[r2][m]            = tot + S->bhhS[r2];   // h_n (+bhh_n)
                S->Bn[r2 - 2 * KU][m]  = gi  + S->bihS[r2];   // i_n (+bih_n)
            }
        }
        if (doPref) S->xs[(t + 1) & 1][pm][pf] = xv;
        __syncthreads();

        // ---- stage 3: gates, new h, DSMEM broadcast to all 8 peers ----
        if (tid < ucnt * KBPC) {
            const int jl = tid >> 2, m = tid & 3;
            const float r = sigm(S->A[jl][m]);
            const float z = sigm(S->A[KU + jl][m]);
            const float n = tanhf(S->Bn[jl][m] + r * S->A[2 * KU + jl][m]);
            const float hn = (1.0f - z) * n + z * S->h[p][u0 + jl][m];
            const uint32_t laddr = smem_u32(&S->h[1 - p][u0 + jl][m]);
            #pragma unroll
            for (int rr = 0; rr < KCL; ++rr) dsmem_store_f32(laddr, rr, hn);
        }
        cluster_sync();   // release remote stores, all CTAs step together
        p ^= 1;
    }

    // final hidden state -> global (each CTA writes its own slice)
    if (tid < ucnt * KBPC) {
        const int jl = tid >> 2, m = tid & 3;
        g_henc[(size_t)(cluster * KBPC + m) * KH + u0 + jl] = S->h[p][u0 + jl][m];
    }
}

// ---------------------------------------------------------------------------
// fc + relu + decoder, fused. One CTA per batch (64 CTAs, 128 threads).
// ---------------------------------------------------------------------------
__global__ void __launch_bounds__(128, 1)
dec_kernel(const float* __restrict__ fcW,  const float* __restrict__ fcb,
           const float* __restrict__ dWih, const float* __restrict__ dWhh,
           const float* __restrict__ dbih, const float* __restrict__ dbhh,
           float* __restrict__ out, int writeEmb)
{
    __shared__ __align__(16) float hb[KH];
    __shared__ __align__(16) float embS[KH];
    __shared__ float dgiS[40];
    __shared__ float whhS[39 * 13];
    __shared__ float bhhS2[40];
    __shared__ float ghS[40];
    __shared__ float hdS[16];

    const int b = blockIdx.x, tid = threadIdx.x;

    for (int i = tid; i < KH; i += 128) hb[i] = g_henc[(size_t)b * KH + i];
    __syncthreads();

    // emb = relu(h_last @ fc_W^T + fc_b)
    for (int j = tid; j < KH; j += 128) {
        const float4* wr = reinterpret_cast<const float4*>(fcW + (size_t)j * KH);
        float s0 = 0.f, s1 = 0.f, s2 = 0.f, s3 = 0.f;
        #pragma unroll 5
        for (int k = 0; k < KH / 4; ++k) {
            const float4 w4 = wr[k];
            const float4 h4 = *reinterpret_cast<const float4*>(&hb[k * 4]);
            s0 = fmaf(w4.x, h4.x, s0); s1 = fmaf(w4.y, h4.y, s1);
            s2 = fmaf(w4.z, h4.z, s2); s3 = fmaf(w4.w, h4.w, s3);
        }
        float s = fcb[j] + ((s0 + s1) + (s2 + s3));
        s = fmaxf(s, 0.0f);
        embS[j] = s;
        if (writeEmb)
            out[(size_t)KB * KT * KF + (size_t)b * KH + j] = s;
    }
    __syncthreads();

    // dgi = emb @ dec_Wih^T + dec_bih   (constant across steps)
    if (tid < 39) {
        const float4* wr = reinterpret_cast<const float4*>(dWih + (size_t)tid * KH);
        float s0 = 0.f, s1 = 0.f, s2 = 0.f, s3 = 0.f;
        #pragma unroll 5
        for (int k = 0; k < KH / 4; ++k) {
            const float4 w4 = wr[k];
            const float4 h4 = *reinterpret_cast<const float4*>(&embS[k * 4]);
            s0 = fmaf(w4.x, h4.x, s0); s1 = fmaf(w4.y, h4.y, s1);
            s2 = fmaf(w4.z, h4.z, s2); s3 = fmaf(w4.w, h4.w, s3);
        }
        dgiS[tid] = dbih[tid] + ((s0 + s1) + (s2 + s3));
    }
    for (int i = tid; i < 39 * 13; i += 128) whhS[i] = dWhh[i];
    if (tid < 39) bhhS2[tid] = dbhh[tid];
    if (tid < 16) hdS[tid] = 0.0f;
    __syncthreads();

    // warp-synchronous decoder loop (warp 0 only)
    if (tid < 32) {
        const int lane = tid;
        const bool two = (lane < 7);           // lanes 0..6 own rows lane+32
        float w0[13], w1[13];
        #pragma unroll
        for (int k = 0; k < 13; ++k) {
            w0[k] = whhS[lane * 13 + k];
            w1[k] = two ? whhS[(lane + 32) * 13 + k] : 0.0f;
        }
        const float bh0 = bhhS2[lane];
        const float bh1 = two ? bhhS2[lane + 32] : 0.0f;
        float dgr = 0.f, dgz = 0.f, dgn = 0.f, hprev = 0.f;
        if (lane < 13) {
            dgr = dgiS[lane];
            dgz = dgiS[13 + lane];
            dgn = dgiS[26 + lane];
        }
        float* op = out + (size_t)b * KT * KF;

        for (int t = 0; t < KT; ++t) {
            float s0 = bh0, s1 = bh1;
            #pragma unroll
            for (int k = 0; k < 13; ++k) {
                const float hk = hdS[k];         // broadcast
                s0 = fmaf(w0[k], hk, s0);
                s1 = fmaf(w1[k], hk, s1);
            }
            ghS[lane] = s0;
            if (two) ghS[lane + 32] = s1;
            __syncwarp();
            if (lane < 13) {
                const float r  = sigm(dgr + ghS[lane]);
                const float z  = sigm(dgz + ghS[13 + lane]);
                const float n  = tanhf(dgn + r * ghS[26 + lane]);
                const float hn = (1.0f - z) * n + z * hprev;
                hprev = hn;
                op[(size_t)t * KF + lane] = hn;
                hdS[lane] = hn;
            }
            __syncwarp();
        }
    }
}

extern "C" void kernel_launch(void* const* d_in, const int* in_sizes, int n_in,
                              void* d_out, int out_size)
{
    const float* x    = (const float*)d_in[0];
    const float* eWih = (const float*)d_in[1];
    const float* eWhh = (const float*)d_in[2];
    const float* ebih = (const float*)d_in[3];
    const float* ebhh = (const float*)d_in[4];
    const float* fcW  = (const float*)d_in[5];
    const float* fcb  = (const float*)d_in[6];
    const float* dWih = (const float*)d_in[7];
    const float* dWhh = (const float*)d_in[8];
    const float* dbih = (const float*)d_in[9];
    const float* dbhh = (const float*)d_in[10];
    float* out = (float*)d_out;

    const int writeEmb = (out_size >= KB * KT * KF + KB * KH) ? 1 : 0;

    cudaFuncSetAttribute(enc_kernel, cudaFuncAttributeMaxDynamicSharedMemorySize,
                         (int)sizeof(EncSmem));

    enc_kernel<<<(KB / KBPC) * KCL, KTHR, sizeof(EncSmem)>>>(x, eWih, eWhh, ebih, ebhh);
    dec_kernel<<<KB, 128>>>(fcW, fcb, dWih, dWhh, dbih, dbhh, out, writeEmb);
}

// round 4
// speedup vs baseline: 1.3300x; 1.3300x over previous
#include <cuda_runtime.h>
#include <cstdint>

// ---------------------------------------------------------------------------
// GRU acoustic model:
//   encoder GRU(13 -> 300) over T=2048 (only final h needed),
//   emb = relu(h_last @ fc_W^T + fc_b),
//   decoder GRU(300 -> 13), constant input emb, T=2048 (all h emitted).
//
// Encoder: 16 clusters x 8 CTAs, 512 thr. Cluster = 4 batches. Each thread
// owns one (gate-row, k-quarter) slice of Whh IN REGISTERS (75 floats, fully
// unrolled). Per step: 75x (LDS.128 broadcast h + 4 FFMA), write partials,
// one syncthreads, then 152 gate threads reduce partials + on-the-fly gi,
// activations, DSMEM push of new h slice to all 8 peers, barrier.cluster.
//
// Decoder (fused with fc): 64 CTAs (one per batch), warp-synchronous loop.
// ---------------------------------------------------------------------------

#define KB   64
#define KT   2048
#define KF   13
#define KH   300
#define KCL  8      // CTAs per cluster
#define KBPC 4      // batches per cluster
#define KU   38     // hidden units per CTA (rank 7 uses 34)
#define KROWS 114   // 3 * KU gate rows per CTA
#define KTHR 512
#define KQ   75     // k-elements per quarter

struct EncSmem {
    float h[2][KH][KBPC];        // double-buffered hidden, [k][batch] (16B rows)
    float part[128][4][KBPC];    // partial sums [row][quarter][batch]
    float WihT[16][128];         // input weights transposed [f][row]
    float bsum[128];             // bih+bhh for r,z rows
    float bihN[64];              // bih for n rows (index jl)
    float bhhN[64];              // bhh for n rows (index jl)
    float xs[2][KBPC][16];       // double-buffered x_t per batch
};

__device__ float g_henc[KB * KH];

__device__ __forceinline__ float sigm(float v) {
    return 1.0f / (1.0f + expf(-v));
}
__device__ __forceinline__ void cluster_sync() {
    asm volatile("barrier.cluster.arrive.aligned;\n\t"
                 "barrier.cluster.wait.aligned;" ::: "memory");
}
__device__ __forceinline__ uint32_t smem_u32(const void* p) {
    uint32_t a;
    asm("{ .reg .u64 t; cvta.to.shared.u64 t, %1; cvt.u32.u64 %0, t; }"
        : "=r"(a) : "l"(p));
    return a;
}
__device__ __forceinline__ void dsmem_store_f32(uint32_t laddr, uint32_t rank, float v) {
    uint32_t ra;
    asm volatile("mapa.shared::cluster.u32 %0, %1, %2;"
                 : "=r"(ra) : "r"(laddr), "r"(rank));
    asm volatile("st.shared::cluster.f32 [%0], %1;" :: "r"(ra), "f"(v) : "memory");
}

__global__ void __cluster_dims__(KCL, 1, 1) __launch_bounds__(KTHR, 1)
enc_kernel(const float* __restrict__ x,   const float* __restrict__ Wih,
           const float* __restrict__ Whh, const float* __restrict__ bih,
           const float* __restrict__ bhh)
{
    __shared__ __align__(16) EncSmem S;
    const int tid     = threadIdx.x;
    const int cluster = blockIdx.x / KCL;
    const int rank    = blockIdx.x % KCL;
    const int u0      = rank * KU;
    const int ucnt    = (KH - u0 < KU) ? (KH - u0) : KU;

    const int row = tid & 127;    // gate row (consecutive lanes)
    const int q   = tid >> 7;     // k-quarter (uniform per warp)

    // ---- init smem ----
    for (int i = tid; i < 2 * KH * KBPC; i += KTHR) (&S.h[0][0][0])[i] = 0.f;
    for (int i = tid; i < 16 * 128; i += KTHR) (&S.WihT[0][0])[i] = 0.f;
    for (int i = tid; i < 128; i += KTHR) S.bsum[i] = 0.f;
    for (int i = tid; i < 64; i += KTHR) { S.bihN[i] = 0.f; S.bhhN[i] = 0.f; }
    __syncthreads();

    for (int i = tid; i < 3 * ucnt * KF; i += KTHR) {
        const int f  = i % KF;
        const int rr = i / KF;
        const int g = rr / ucnt, jl = rr % ucnt;
        S.WihT[f][g * KU + jl] = Wih[(size_t)(g * KH + u0 + jl) * KF + f];
    }
    if (tid < KROWS) {
        const int g = tid / KU, jl = tid % KU;
        if (jl < ucnt) {
            const float bi = bih[g * KH + u0 + jl];
            const float bh = bhh[g * KH + u0 + jl];
            if (g < 2) S.bsum[tid] = bi + bh;
            else       { S.bihN[jl] = bi; S.bhhN[jl] = bh; }
        }
    }
    if (tid < KBPC * KF) {
        const int m = tid / KF, f = tid % KF;
        S.xs[0][m][f] = x[((size_t)(cluster * KBPC + m) * KT + 0) * KF + f];
    }

    // ---- load this thread's Whh slice into registers ----
    float W[KQ];
    {
        const int g = row / KU, jl = row % KU;
        const bool active = (row < KROWS) && (jl < ucnt);
        if (active) {
            const float* wr = Whh + (size_t)(g * KH + u0 + jl) * KH + q * KQ;
            #pragma unroll
            for (int i = 0; i < KQ; ++i) W[i] = wr[i];
        } else {
            #pragma unroll
            for (int i = 0; i < KQ; ++i) W[i] = 0.f;
        }
    }
    __syncthreads();
    cluster_sync();   // all peers initialized before any remote store

    int p = 0;
    float4* partOut = reinterpret_cast<float4*>(&S.part[row][q][0]);

    for (int t = 0; t < KT; ++t) {
        // prefetch next step's x into registers (LDG overlaps stage 1)
        float xv = 0.f; int pm = 0, pf = 0;
        const bool doPref = (tid < KBPC * KF) && (t + 1 < KT);
        if (doPref) {
            pm = tid / KF; pf = tid % KF;
            xv = x[((size_t)(cluster * KBPC + pm) * KT + (t + 1)) * KF + pf];
        }

        // ---- stage 1: partial gh over this thread's quarter (W in regs) ----
        {
            const float4* hq =
                reinterpret_cast<const float4*>(&S.h[p][0][0]) + q * KQ;
            float a0 = 0.f, a1 = 0.f, a2 = 0.f, a3 = 0.f;
            #pragma unroll
            for (int i = 0; i < KQ; ++i) {
                const float4 hv = hq[i];          // broadcast, immediate offset
                a0 = fmaf(W[i], hv.x, a0);
                a1 = fmaf(W[i], hv.y, a1);
                a2 = fmaf(W[i], hv.z, a2);
                a3 = fmaf(W[i], hv.w, a3);
            }
            *partOut = make_float4(a0, a1, a2, a3);
        }
        __syncthreads();

        // ---- stage 2+3 merged: reduce, gi, gates, DSMEM broadcast ----
        if (tid < KBPC * KU) {
            const int jl = tid >> 2, m = tid & 3;
            if (jl < ucnt) {
                float pr = 0.f, pz = 0.f, pn = 0.f;
                #pragma unroll
                for (int qq = 0; qq < 4; ++qq) {
                    pr += S.part[jl][qq][m];
                    pz += S.part[KU + jl][qq][m];
                    pn += S.part[2 * KU + jl][qq][m];
                }
                const float* xr = S.xs[t & 1][m];
                float gr = 0.f, gz = 0.f, gn = 0.f;
                #pragma unroll
                for (int f = 0; f < KF; ++f) {
                    const float xf = xr[f];
                    gr = fmaf(S.WihT[f][jl], xf, gr);
                    gz = fmaf(S.WihT[f][KU + jl], xf, gz);
                    gn = fmaf(S.WihT[f][2 * KU + jl], xf, gn);
                }
                const float r = sigm(pr + gr + S.bsum[jl]);
                const float z = sigm(pz + gz + S.bsum[KU + jl]);
                const float n = tanhf(gn + S.bihN[jl] + r * (pn + S.bhhN[jl]));
                const float hn = (1.0f - z) * n + z * S.h[p][u0 + jl][m];
                const uint32_t la = smem_u32(&S.h[1 - p][u0 + jl][m]);
                #pragma unroll
                for (int rr = 0; rr < KCL; ++rr) dsmem_store_f32(la, rr, hn);
            }
        }
        if (doPref) S.xs[(t + 1) & 1][pm][pf] = xv;
        cluster_sync();   // drains remote stores; all CTAs step together
        p ^= 1;
    }

    // final hidden state -> global (each CTA writes its own slice)
    if (tid < ucnt * KBPC) {
        const int jl = tid >> 2, m = tid & 3;
        g_henc[(size_t)(cluster * KBPC + m) * KH + u0 + jl] = S.h[p][u0 + jl][m];
    }
}

// ---------------------------------------------------------------------------
// fc + relu + decoder, fused. One CTA per batch (64 CTAs, 128 threads).
// ---------------------------------------------------------------------------
__global__ void __launch_bounds__(128, 1)
dec_kernel(const float* __restrict__ fcW,  const float* __restrict__ fcb,
           const float* __restrict__ dWih, const float* __restrict__ dWhh,
           const float* __restrict__ dbih, const float* __restrict__ dbhh,
           float* __restrict__ out, int writeEmb)
{
    __shared__ __align__(16) float hb[KH];
    __shared__ __align__(16) float embS[KH];
    __shared__ float dgiS[40];
    __shared__ float whhS[39 * 13];
    __shared__ float bhhS2[40];
    __shared__ float ghS[40];
    __shared__ float hdS[16];

    const int b = blockIdx.x, tid = threadIdx.x;

    for (int i = tid; i < KH; i += 128) hb[i] = g_henc[(size_t)b * KH + i];
    __syncthreads();

    // emb = relu(h_last @ fc_W^T + fc_b)
    for (int j = tid; j < KH; j += 128) {
        const float4* wr = reinterpret_cast<const float4*>(fcW + (size_t)j * KH);
        float s0 = 0.f, s1 = 0.f, s2 = 0.f, s3 = 0.f;
        #pragma unroll 5
        for (int k = 0; k < KH / 4; ++k) {
            const float4 w4 = wr[k];
            const float4 h4 = *reinterpret_cast<const float4*>(&hb[k * 4]);
            s0 = fmaf(w4.x, h4.x, s0); s1 = fmaf(w4.y, h4.y, s1);
            s2 = fmaf(w4.z, h4.z, s2); s3 = fmaf(w4.w, h4.w, s3);
        }
        float s = fcb[j] + ((s0 + s1) + (s2 + s3));
        s = fmaxf(s, 0.0f);
        embS[j] = s;
        if (writeEmb)
            out[(size_t)KB * KT * KF + (size_t)b * KH + j] = s;
    }
    __syncthreads();

    // dgi = emb @ dec_Wih^T + dec_bih (constant across steps)
    if (tid < 39) {
        const float4* wr = reinterpret_cast<const float4*>(dWih + (size_t)tid * KH);
        float s0 = 0.f, s1 = 0.f, s2 = 0.f, s3 = 0.f;
        #pragma unroll 5
        for (int k = 0; k < KH / 4; ++k) {
            const float4 w4 = wr[k];
            const float4 h4 = *reinterpret_cast<const float4*>(&embS[k * 4]);
            s0 = fmaf(w4.x, h4.x, s0); s1 = fmaf(w4.y, h4.y, s1);
            s2 = fmaf(w4.z, h4.z, s2); s3 = fmaf(w4.w, h4.w, s3);
        }
        dgiS[tid] = dbih[tid] + ((s0 + s1) + (s2 + s3));
    }
    for (int i = tid; i < 39 * 13; i += 128) whhS[i] = dWhh[i];
    if (tid < 39) bhhS2[tid] = dbhh[tid];
    if (tid < 16) hdS[tid] = 0.0f;
    __syncthreads();

    // warp-synchronous decoder loop (warp 0 only)
    if (tid < 32) {
        const int lane = tid;
        const bool two = (lane < 7);          // lanes 0..6 own rows lane+32
        float w0[13], w1[13];
        #pragma unroll
        for (int k = 0; k < 13; ++k) {
            w0[k] = whhS[lane * 13 + k];
            w1[k] = two ? whhS[(lane + 32) * 13 + k] : 0.0f;
        }
        const float bh0 = bhhS2[lane];
        const float bh1 = two ? bhhS2[lane + 32] : 0.0f;
        float dgr = 0.f, dgz = 0.f, dgn = 0.f, hprev = 0.f;
        if (lane < 13) {
            dgr = dgiS[lane];
            dgz = dgiS[13 + lane];
            dgn = dgiS[26 + lane];
        }
        float* op = out + (size_t)b * KT * KF;

        for (int t = 0; t < KT; ++t) {
            float s0 = bh0, s1 = bh1;
            #pragma unroll
            for (int k = 0; k < 13; ++k) {
                const float hk = hdS[k];        // broadcast
                s0 = fmaf(w0[k], hk, s0);
                s1 = fmaf(w1[k], hk, s1);
            }
            ghS[lane] = s0;
            if (two) ghS[lane + 32] = s1;
            __syncwarp();
            if (lane < 13) {
                const float r  = sigm(dgr + ghS[lane]);
                const float z  = sigm(dgz + ghS[13 + lane]);
                const float n  = tanhf(dgn + r * ghS[26 + lane]);
                const float hn = (1.0f - z) * n + z * hprev;
                hprev = hn;
                op[(size_t)t * KF + lane] = hn;
                hdS[lane] = hn;
            }
            __syncwarp();
        }
    }
}

extern "C" void kernel_launch(void* const* d_in, const int* in_sizes, int n_in,
                              void* d_out, int out_size)
{
    const float* x    = (const float*)d_in[0];
    const float* eWih = (const float*)d_in[1];
    const float* eWhh = (const float*)d_in[2];
    const float* ebih = (const float*)d_in[3];
    const float* ebhh = (const float*)d_in[4];
    const float* fcW  = (const float*)d_in[5];
    const float* fcb  = (const float*)d_in[6];
    const float* dWih = (const float*)d_in[7];
    const float* dWhh = (const float*)d_in[8];
    const float* dbih = (const float*)d_in[9];
    const float* dbhh = (const float*)d_in[10];
    float* out = (float*)d_out;

    const int writeEmb = (out_size >= KB * KT * KF + KB * KH) ? 1 : 0;

    enc_kernel<<<(KB / KBPC) * KCL, KTHR>>>(x, eWih, eWhh, ebih, ebhh);
    dec_kernel<<<KB, 128>>>(fcW, fcb, dWih, dWhh, dbih, dbhh, out, writeEmb);
}

// round 7
// speedup vs baseline: 1.3916x; 1.0463x over previous
#include <cuda_runtime.h>
#include <cstdint>

// ---------------------------------------------------------------------------
// GRU acoustic model (encoder GRU 13->300, fc+relu, decoder GRU 300->13).
//
// Encoder: 16 clusters x 8 CTAs, 512 thr. Cluster = 4 batches. Each thread
// owns one (gate-row, k-quarter) slice of Whh as 38 PACKED f32x2 k-pairs in
// registers. h is stored [batch][k] so {h_k,h_k+1} loads as one LDS.64.
// Stage 1 uses fma.rn.f32x2 (2 MACs/instr). Tail: reduce + on-the-fly gi +
// fast activations + DSMEM push of new h slice to all 8 peers (hoisted mapa),
// one barrier.cluster per step.
// ---------------------------------------------------------------------------

#define KB   64
#define KT   2048
#define KF   13
#define KH   300
#define KCL  8      // CTAs per cluster
#define KBPC 4      // batches per cluster
#define KU   38     // hidden units per CTA (rank 7 uses 34)
#define KROWS 114   // 3 * KU gate rows per CTA
#define KTHR 512
#define KPAIRS 38   // k-pairs per quarter (76 k, last quarter zero-padded)
#define KHP  308    // padded k extent per batch row

typedef unsigned long long u64t;

struct EncSmem {
    float h[2][KBPC][KHP];       // double-buffered hidden, [buf][batch][k]
    float part[128][18];         // partials [row][q*4+m], padded (2-way max)
    float WihT[16][128];         // input weights transposed [f][row]
    float bsum[128];             // bih+bhh for r,z rows
    float bihN[64];              // bih for n rows (jl)
    float bhhN[64];              // bhh for n rows (jl)
    float xs[2][KBPC][16];       // double-buffered x_t per batch
};

__device__ float g_henc[KB * KH];

__device__ __forceinline__ float sigm_fast(float v) {
    return __fdividef(1.0f, 1.0f + __expf(-v));
}
__device__ __forceinline__ float tanh_fast(float v) {
    return __fdividef(2.0f, 1.0f + __expf(-2.0f * v)) - 1.0f;
}
__device__ __forceinline__ void cluster_sync() {
    asm volatile("barrier.cluster.arrive.aligned;\n\t"
                 "barrier.cluster.wait.aligned;" ::: "memory");
}
__device__ __forceinline__ uint32_t smem_u32(const void* p) {
    uint32_t a;
    asm("{ .reg .u64 t; cvta.to.shared.u64 t, %1; cvt.u32.u64 %0, t; }"
        : "=r"(a) : "l"(p));
    return a;
}
__device__ __forceinline__ uint32_t mapa_u32(uint32_t laddr, uint32_t rank) {
    uint32_t ra;
    asm("mapa.shared::cluster.u32 %0, %1, %2;" : "=r"(ra) : "r"(laddr), "r"(rank));
    return ra;
}
__device__ __forceinline__ void st_cluster_f32(uint32_t addr, float v) {
    asm volatile("st.shared::cluster.f32 [%0], %1;" :: "r"(addr), "f"(v) : "memory");
}
__device__ __forceinline__ u64t lds_b64(uint32_t addr) {
    u64t v;
    asm volatile("ld.shared.b64 %0, [%1];" : "=l"(v) : "r"(addr));
    return v;
}
__device__ __forceinline__ u64t pack2(float lo, float hi) {
    u64t v;
    asm("mov.b64 %0, {%1, %2};" : "=l"(v) : "f"(lo), "f"(hi));
    return v;
}
__device__ __forceinline__ void unpack2(u64t v, float& lo, float& hi) {
    asm("mov.b64 {%0, %1}, %2;" : "=f"(lo), "=f"(hi) : "l"(v));
}
__device__ __forceinline__ void fma2(u64t& d, u64t a, u64t b) {
    asm("fma.rn.f32x2 %0, %1, %2, %0;" : "+l"(d) : "l"(a), "l"(b));
}

__global__ void __cluster_dims__(KCL, 1, 1) __launch_bounds__(KTHR, 1)
enc_kernel(const float* __restrict__ x,   const float* __restrict__ Wih,
           const float* __restrict__ Whh, const float* __restrict__ bih,
           const float* __restrict__ bhh)
{
    __shared__ __align__(16) EncSmem S;
    const int tid     = threadIdx.x;
    const int cluster = blockIdx.x / KCL;
    const int rank    = blockIdx.x % KCL;
    const int u0      = rank * KU;
    const int ucnt    = (KH - u0 < KU) ? (KH - u0) : KU;

    const int row = tid & 127;    // gate row (consecutive lanes)
    const int q   = tid >> 7;     // k-quarter (uniform per warp)
    const int k0  = q * 2 * KPAIRS;  // 0,76,152,228

    // ---- init smem ----
    for (int i = tid; i < 2 * KBPC * KHP; i += KTHR) (&S.h[0][0][0])[i] = 0.f;
    for (int i = tid; i < 16 * 128; i += KTHR) (&S.WihT[0][0])[i] = 0.f;
    for (int i = tid; i < 128; i += KTHR) S.bsum[i] = 0.f;
    for (int i = tid; i < 64; i += KTHR) { S.bihN[i] = 0.f; S.bhhN[i] = 0.f; }
    __syncthreads();

    for (int i = tid; i < 3 * ucnt * KF; i += KTHR) {
        const int f  = i % KF;
        const int rr = i / KF;
        const int g = rr / ucnt, jl = rr % ucnt;
        S.WihT[f][g * KU + jl] = Wih[(size_t)(g * KH + u0 + jl) * KF + f];
    }
    if (tid < KROWS) {
        const int g = tid / KU, jl = tid % KU;
        if (jl < ucnt) {
            const float bi = bih[g * KH + u0 + jl];
            const float bh = bhh[g * KH + u0 + jl];
            if (g < 2) S.bsum[tid] = bi + bh;
            else       { S.bihN[jl] = bi; S.bhhN[jl] = bh; }
        }
    }
    if (tid < KBPC * KF) {
        const int m = tid / KF, f = tid % KF;
        S.xs[0][m][f] = x[((size_t)(cluster * KBPC + m) * KT + 0) * KF + f];
    }

    // ---- load this thread's packed Whh k-pairs into registers ----
    u64t W2[KPAIRS];
    {
        const int g = row / KU, jl = row % KU;
        const bool active = (row < KROWS) && (jl < ucnt);
        const float* wr = active ? (Whh + (size_t)(g * KH + u0 + jl) * KH) : Whh;
        #pragma unroll
        for (int i = 0; i < KPAIRS; ++i) {
            const int k = k0 + 2 * i;
            float w0 = 0.f, w1 = 0.f;
            if (active && k < KH)     w0 = wr[k];
            if (active && k + 1 < KH) w1 = wr[k + 1];
            W2[i] = pack2(w0, w1);
        }
    }

    // ---- hoisted DSMEM peer base addresses + step offsets ----
    const uint32_t hbaseL = smem_u32(&S.h[0][0][0]);
    uint32_t R0 = mapa_u32(hbaseL, 0), R1 = mapa_u32(hbaseL, 1),
             R2 = mapa_u32(hbaseL, 2), R3 = mapa_u32(hbaseL, 3),
             R4 = mapa_u32(hbaseL, 4), R5 = mapa_u32(hbaseL, 5),
             R6 = mapa_u32(hbaseL, 6), R7 = mapa_u32(hbaseL, 7);
    const int jl_t = tid >> 2, m_t = tid & 3;          // tail mapping
    const uint32_t offA = ((KBPC + m_t) * KHP + u0 + jl_t) * 4;  // write h[1]
    const uint32_t offB = ((m_t) * KHP + u0 + jl_t) * 4;         // write h[0]

    __syncthreads();
    cluster_sync();   // all peers initialized before any remote store

    int p = 0;

    for (int t = 0; t < KT; ++t) {
        // prefetch next step's x into registers (LDG overlaps stage 1)
        float xv = 0.f; int pm = 0, pf = 0;
        const bool doPref = (tid < KBPC * KF) && (t + 1 < KT);
        if (doPref) {
            pm = tid / KF; pf = tid % KF;
            xv = x[((size_t)(cluster * KBPC + pm) * KT + (t + 1)) * KF + pf];
        }

        // ---- stage 1: packed partial gh over this thread's quarter ----
        {
            const uint32_t hb = hbaseL + (uint32_t)(p * KBPC * KHP + k0) * 4;
            const uint32_t a0 = hb;
            const uint32_t a1 = hb + KHP * 4;
            const uint32_t a2 = hb + 2 * KHP * 4;
            const uint32_t a3 = hb + 3 * KHP * 4;
            u64t c0 = 0ULL, c1 = 0ULL, c2 = 0ULL, c3 = 0ULL;
            #pragma unroll
            for (int i = 0; i < KPAIRS; ++i) {
                const u64t w = W2[i];
                fma2(c0, w, lds_b64(a0 + i * 8));
                fma2(c1, w, lds_b64(a1 + i * 8));
                fma2(c2, w, lds_b64(a2 + i * 8));
                fma2(c3, w, lds_b64(a3 + i * 8));
            }
            float l0, h0, l1, h1, l2, h2, l3, h3;
            unpack2(c0, l0, h0); unpack2(c1, l1, h1);
            unpack2(c2, l2, h2); unpack2(c3, l3, h3);
            float* pr = &S.part[row][q * 4];
            pr[0] = l0 + h0; pr[1] = l1 + h1;
            pr[2] = l2 + h2; pr[3] = l3 + h3;
        }
        __syncthreads();

        // ---- tail: reduce, gi, gates, DSMEM broadcast ----
        if (tid < KBPC * KU && jl_t < ucnt) {
            const int jl = jl_t, m = m_t;
            const float* pR = S.part[jl];
            const float* pZ = S.part[KU + jl];
            const float* pN = S.part[2 * KU + jl];
            float pr = pR[m] + pR[4 + m] + pR[8 + m] + pR[12 + m];
            float pz = pZ[m] + pZ[4 + m] + pZ[8 + m] + pZ[12 + m];
            float pn = pN[m] + pN[4 + m] + pN[8 + m] + pN[12 + m];
            const float* xr = S.xs[t & 1][m];
            float gr = 0.f, gz = 0.f, gn = 0.f;
            #pragma unroll
            for (int f = 0; f < KF; ++f) {
                const float xf = xr[f];
                gr = fmaf(S.WihT[f][jl], xf, gr);
                gz = fmaf(S.WihT[f][KU + jl], xf, gz);
                gn = fmaf(S.WihT[f][2 * KU + jl], xf, gn);
            }
            const float r = sigm_fast(pr + gr + S.bsum[jl]);
            const float z = sigm_fast(pz + gz + S.bsum[KU + jl]);
            const float n = tanh_fast(gn + S.bihN[jl] + r * (pn + S.bhhN[jl]));
            const float hn = (1.0f - z) * n + z * S.h[p][m][u0 + jl];
            const uint32_t off = p ? offB : offA;
            st_cluster_f32(R0 + off, hn); st_cluster_f32(R1 + off, hn);
            st_cluster_f32(R2 + off, hn); st_cluster_f32(R3 + off, hn);
            st_cluster_f32(R4 + off, hn); st_cluster_f32(R5 + off, hn);
            st_cluster_f32(R6 + off, hn); st_cluster_f32(R7 + off, hn);
        }
        if (doPref) S.xs[(t + 1) & 1][pm][pf] = xv;
        cluster_sync();   // drains remote stores; all CTAs step together
        p ^= 1;
    }

    // final hidden state -> global (each CTA writes its own slice)
    if (tid < ucnt * KBPC) {
        g_henc[(size_t)(cluster * KBPC + m_t) * KH + u0 + jl_t] =
            S.h[p][m_t][u0 + jl_t];
    }
}

// ---------------------------------------------------------------------------
// fc + relu + decoder, fused. One CTA per batch (64 CTAs, 128 threads).
// ---------------------------------------------------------------------------
__device__ __forceinline__ float sigm_p(float v) {
    return 1.0f / (1.0f + expf(-v));
}

__global__ void __launch_bounds__(128, 1)
dec_kernel(const float* __restrict__ fcW,  const float* __restrict__ fcb,
           const float* __restrict__ dWih, const float* __restrict__ dWhh,
           const float* __restrict__ dbih, const float* __restrict__ dbhh,
           float* __restrict__ out, int writeEmb)
{
    __shared__ __align__(16) float hb[KH];
    __shared__ __align__(16) float embS[KH];
    __shared__ float dgiS[40];
    __shared__ float whhS[39 * 13];
    __shared__ float bhhS2[40];
    __shared__ float ghS[40];
    __shared__ float hdS[16];

    const int b = blockIdx.x, tid = threadIdx.x;

    for (int i = tid; i < KH; i += 128) hb[i] = g_henc[(size_t)b * KH + i];
    __syncthreads();

    for (int j = tid; j < KH; j += 128) {
        const float4* wr = reinterpret_cast<const float4*>(fcW + (size_t)j * KH);
        float s0 = 0.f, s1 = 0.f, s2 = 0.f, s3 = 0.f;
        #pragma unroll 5
        for (int k = 0; k < KH / 4; ++k) {
            const float4 w4 = wr[k];
            const float4 h4 = *reinterpret_cast<const float4*>(&hb[k * 4]);
            s0 = fmaf(w4.x, h4.x, s0); s1 = fmaf(w4.y, h4.y, s1);
            s2 = fmaf(w4.z, h4.z, s2); s3 = fmaf(w4.w, h4.w, s3);
        }
        float s = fcb[j] + ((s0 + s1) + (s2 + s3));
        s = fmaxf(s, 0.0f);
        embS[j] = s;
        if (writeEmb)
            out[(size_t)KB * KT * KF + (size_t)b * KH + j] = s;
    }
    __syncthreads();

    if (tid < 39) {
        const float4* wr = reinterpret_cast<const float4*>(dWih + (size_t)tid * KH);
        float s0 = 0.f, s1 = 0.f, s2 = 0.f, s3 = 0.f;
        #pragma unroll 5
        for (int k = 0; k < KH / 4; ++k) {
            const float4 w4 = wr[k];
            const float4 h4 = *reinterpret_cast<const float4*>(&embS[k * 4]);
            s0 = fmaf(w4.x, h4.x, s0); s1 = fmaf(w4.y, h4.y, s1);
            s2 = fmaf(w4.z, h4.z, s2); s3 = fmaf(w4.w, h4.w, s3);
        }
        dgiS[tid] = dbih[tid] + ((s0 + s1) + (s2 + s3));
    }
    for (int i = tid; i < 39 * 13; i += 128) whhS[i] = dWhh[i];
    if (tid < 39) bhhS2[tid] = dbhh[tid];
    if (tid < 16) hdS[tid] = 0.0f;
    __syncthreads();

    if (tid < 32) {
        const int lane = tid;
        const bool two = (lane < 7);
        float w0[13], w1[13];
        #pragma unroll
        for (int k = 0; k < 13; ++k) {
            w0[k] = whhS[lane * 13 + k];
            w1[k] = two ? whhS[(lane + 32) * 13 + k] : 0.0f;
        }
        const float bh0 = bhhS2[lane];
        const float bh1 = two ? bhhS2[lane + 32] : 0.0f;
        float dgr = 0.f, dgz = 0.f, dgn = 0.f, hprev = 0.f;
        if (lane < 13) {
            dgr = dgiS[lane];
            dgz = dgiS[13 + lane];
            dgn = dgiS[26 + lane];
        }
        float* op = out + (size_t)b * KT * KF;

        for (int t = 0; t < KT; ++t) {
            float s0 = bh0, s1 = bh1;
            #pragma unroll
            for (int k = 0; k < 13; ++k) {
                const float hk = hdS[k];
                s0 = fmaf(w0[k], hk, s0);
                s1 = fmaf(w1[k], hk, s1);
            }
            ghS[lane] = s0;
            if (two) ghS[lane + 32] = s1;
            __syncwarp();
            if (lane < 13) {
                const float r  = sigm_p(dgr + ghS[lane]);
                const float z  = sigm_p(dgz + ghS[13 + lane]);
                const float n  = tanhf(dgn + r * ghS[26 + lane]);
                const float hn = (1.0f - z) * n + z * hprev;
                hprev = hn;
                op[(size_t)t * KF + lane] = hn;
                hdS[lane] = hn;
            }
            __syncwarp();
        }
    }
}

// no-op kernels: shift launch parity so ncu (-s 5 -c 1) captures enc_kernel
__global__ void nop_kernel() {}

extern "C" void kernel_launch(void* const* d_in, const int* in_sizes, int n_in,
                              void* d_out, int out_size)
{
    const float* x    = (const float*)d_in[0];
    const float* eWih = (const float*)d_in[1];
    const float* eWhh = (const float*)d_in[2];
    const float* ebih = (const float*)d_in[3];
    const float* ebhh = (const float*)d_in[4];
    const float* fcW  = (const float*)d_in[5];
    const float* fcb  = (const float*)d_in[6];
    const float* dWih = (const float*)d_in[7];
    const float* dWhh = (const float*)d_in[8];
    const float* dbih = (const float*)d_in[9];
    const float* dbhh = (const float*)d_in[10];
    float* out = (float*)d_out;

    const int writeEmb = (out_size >= KB * KT * KF + KB * KH) ? 1 : 0;

    enc_kernel<<<(KB / KBPC) * KCL, KTHR>>>(x, eWih, eWhh, ebih, ebhh);
    dec_kernel<<<KB, 128>>>(fcW, fcb, dWih, dWhh, dbih, dbhh, out, writeEmb);
    nop_kernel<<<1, 32>>>();
    nop_kernel<<<1, 32>>>();
    nop_kernel<<<1, 32>>>();
}

// round 8
// speedup vs baseline: 1.5742x; 1.1313x over previous
#include <cuda_runtime.h>
#include <cstdint>

// ---------------------------------------------------------------------------
// Fully fused GRU acoustic model (single kernel):
//   encoder GRU(13->300) T=2048, fc+relu, decoder GRU(300->13) T=2048.
//
// 16 clusters x 8 CTAs x 512 thr. Cluster = 4 batches. Encoder: each thread
// owns TWO gate-rows x one k-chunk (38 k = 19 pairs) of Whh packed f32x2 in
// registers; each LDS.64 h-pair feeds 2 FFMA2 (halves crossbar bytes).
// Tail: 8-chunk reduce + on-the-fly gi + fast gates + DSMEM push of the new
// h slice to all 8 peers, one barrier.cluster per step.
// After the encoder loop, ranks 0-3 run fc + shuffle-based decoder for their
// batch (cluster-local dependency; no grid sync).
// ---------------------------------------------------------------------------

#define KB   64
#define KT   2048
#define KF   13
#define KH   300
#define KCL  8      // CTAs per cluster
#define KBPC 4      // batches per cluster
#define KU   38     // hidden units per CTA (rank 7 uses 34)
#define KROWS 114   // 3 * KU gate rows per CTA
#define KTHR 512
#define KHP  304    // padded k extent per batch row
#define NCH  8      // k-chunks
#define CPAIR 19    // k-pairs per chunk (38 k)
#define PSTR 36     // part row stride in floats (16B-aligned rows)

typedef unsigned long long u64t;

struct EncSmem {
    float h[2][KBPC][KHP];       // double-buffered hidden, [buf][batch][k]
    float part[KROWS][PSTR];     // partials [row][chunk*4+batch]; also reused
                                 // post-encoder as emb/dgi scratch
    float WihT[16][128];         // input weights transposed [f][row]
    float bsum[128];             // bih+bhh for r,z rows
    float bihN[64];              // bih for n rows (jl)
    float bhhN[64];              // bhh for n rows (jl)
    float xs[2][KBPC][16];       // double-buffered x_t per batch
};

__device__ __forceinline__ float sigm_fast(float v) {
    return __fdividef(1.0f, 1.0f + __expf(-v));
}
__device__ __forceinline__ float tanh_fast(float v) {
    return __fdividef(2.0f, 1.0f + __expf(-2.0f * v)) - 1.0f;
}
__device__ __forceinline__ void cluster_sync() {
    asm volatile("barrier.cluster.arrive.aligned;\n\t"
                 "barrier.cluster.wait.aligned;" ::: "memory");
}
__device__ __forceinline__ uint32_t smem_u32(const void* p) {
    uint32_t a;
    asm("{ .reg .u64 t; cvta.to.shared.u64 t, %1; cvt.u32.u64 %0, t; }"
        : "=r"(a) : "l"(p));
    return a;
}
__device__ __forceinline__ uint32_t mapa_u32(uint32_t laddr, uint32_t rank) {
    uint32_t ra;
    asm("mapa.shared::cluster.u32 %0, %1, %2;" : "=r"(ra) : "r"(laddr), "r"(rank));
    return ra;
}
__device__ __forceinline__ void st_cluster_f32(uint32_t addr, float v) {
    asm volatile("st.shared::cluster.f32 [%0], %1;" :: "r"(addr), "f"(v) : "memory");
}
__device__ __forceinline__ u64t lds_b64(uint32_t addr) {
    u64t v;
    asm volatile("ld.shared.b64 %0, [%1];" : "=l"(v) : "r"(addr));
    return v;
}
__device__ __forceinline__ u64t pack2(float lo, float hi) {
    u64t v;
    asm("mov.b64 %0, {%1, %2};" : "=l"(v) : "f"(lo), "f"(hi));
    return v;
}
__device__ __forceinline__ float hadd2(u64t v) {
    float lo, hi;
    asm("mov.b64 {%0, %1}, %2;" : "=f"(lo), "=f"(hi) : "l"(v));
    return lo + hi;
}
__device__ __forceinline__ void fma2(u64t& d, u64t a, u64t b) {
    asm("fma.rn.f32x2 %0, %1, %2, %0;" : "+l"(d) : "l"(a), "l"(b));
}

__global__ void __cluster_dims__(KCL, 1, 1) __launch_bounds__(KTHR, 1)
enc_kernel(const float* __restrict__ x,    const float* __restrict__ Wih,
           const float* __restrict__ Whh,  const float* __restrict__ bih,
           const float* __restrict__ bhh,
           const float* __restrict__ fcW,  const float* __restrict__ fcb,
           const float* __restrict__ dWih, const float* __restrict__ dWhh,
           const float* __restrict__ dbih, const float* __restrict__ dbhh,
           float* __restrict__ out, int writeEmb)
{
    __shared__ __align__(16) EncSmem S;
    const int tid     = threadIdx.x;
    const int cluster = blockIdx.x / KCL;
    const int rank    = blockIdx.x % KCL;
    const int u0      = rank * KU;
    const int ucnt    = (KH - u0 < KU) ? (KH - u0) : KU;

    const int rp = tid & 63;       // row-pair index, active < 57
    const int c  = tid >> 6;       // k-chunk 0..7 (uniform per warp)
    const int r0 = 2 * rp;         // gate rows r0, r0+1
    const int k0 = c * 38;

    // ---- init smem ----
    for (int i = tid; i < 2 * KBPC * KHP; i += KTHR) (&S.h[0][0][0])[i] = 0.f;
    for (int i = tid; i < 16 * 128; i += KTHR) (&S.WihT[0][0])[i] = 0.f;
    for (int i = tid; i < 128; i += KTHR) S.bsum[i] = 0.f;
    for (int i = tid; i < 64; i += KTHR) { S.bihN[i] = 0.f; S.bhhN[i] = 0.f; }
    __syncthreads();

    for (int i = tid; i < 3 * ucnt * KF; i += KTHR) {
        const int f  = i % KF;
        const int rr = i / KF;
        const int g = rr / ucnt, jl = rr % ucnt;
        S.WihT[f][g * KU + jl] = Wih[(size_t)(g * KH + u0 + jl) * KF + f];
    }
    if (tid < KROWS) {
        const int g = tid / KU, jl = tid % KU;
        if (jl < ucnt) {
            const float bi = bih[g * KH + u0 + jl];
            const float bh = bhh[g * KH + u0 + jl];
            if (g < 2) S.bsum[tid] = bi + bh;
            else       { S.bihN[jl] = bi; S.bhhN[jl] = bh; }
        }
    }
    if (tid < KBPC * KF) {
        const int m = tid / KF, f = tid % KF;
        S.xs[0][m][f] = x[((size_t)(cluster * KBPC + m) * KT + 0) * KF + f];
    }

    // ---- load this thread's TWO gate-rows of packed Whh k-pairs ----
    u64t Wa[CPAIR], Wb[CPAIR];
    {
        const int ga = r0 / KU,       jla = r0 % KU;
        const int gb = (r0 + 1) / KU, jlb = (r0 + 1) % KU;
        const bool actA = (rp < 57) && (r0 < KROWS)     && (jla < ucnt);
        const bool actB = (rp < 57) && (r0 + 1 < KROWS) && (jlb < ucnt);
        const float* wrA = actA ? (Whh + (size_t)(ga * KH + u0 + jla) * KH) : Whh;
        const float* wrB = actB ? (Whh + (size_t)(gb * KH + u0 + jlb) * KH) : Whh;
        #pragma unroll
        for (int i = 0; i < CPAIR; ++i) {
            const int k = k0 + 2 * i;
            float a0 = 0.f, a1 = 0.f, b0 = 0.f, b1 = 0.f;
            if (actA && k < KH)     a0 = wrA[k];
            if (actA && k + 1 < KH) a1 = wrA[k + 1];
            if (actB && k < KH)     b0 = wrB[k];
            if (actB && k + 1 < KH) b1 = wrB[k + 1];
            Wa[i] = pack2(a0, a1);
            Wb[i] = pack2(b0, b1);
        }
    }

    // ---- hoisted DSMEM peer base addresses + step offsets ----
    const uint32_t hbaseL = smem_u32(&S.h[0][0][0]);
    uint32_t R0 = mapa_u32(hbaseL, 0), R1 = mapa_u32(hbaseL, 1),
             R2 = mapa_u32(hbaseL, 2), R3 = mapa_u32(hbaseL, 3),
             R4 = mapa_u32(hbaseL, 4), R5 = mapa_u32(hbaseL, 5),
             R6 = mapa_u32(hbaseL, 6), R7 = mapa_u32(hbaseL, 7);
    const int jl_t = tid >> 2, m_t = tid & 3;                    // tail mapping
    const uint32_t offA = ((KBPC + m_t) * KHP + u0 + jl_t) * 4;  // write h[1]
    const uint32_t offB = ((m_t) * KHP + u0 + jl_t) * 4;         // write h[0]

    __syncthreads();
    cluster_sync();   // all peers initialized before any remote store

    int p = 0;

    for (int t = 0; t < KT; ++t) {
        // prefetch next step's x into registers (LDG overlaps stage 1)
        float xv = 0.f; int pm = 0, pf = 0;
        const bool doPref = (tid < KBPC * KF) && (t + 1 < KT);
        if (doPref) {
            pm = tid / KF; pf = tid % KF;
            xv = x[((size_t)(cluster * KBPC + pm) * KT + (t + 1)) * KF + pf];
        }

        // ---- stage 1: two rows x one chunk, each h pair feeds 2 FFMA2 ----
        if (rp < 57) {
            const uint32_t hb = hbaseL + (uint32_t)(p * KBPC * KHP + k0) * 4;
            u64t A0 = 0, A1 = 0, A2 = 0, A3 = 0;   // row r0, batches 0..3
            u64t B0 = 0, B1 = 0, B2 = 0, B3 = 0;   // row r0+1
            #pragma unroll
            for (int i = 0; i < CPAIR; ++i) {
                const u64t h0 = lds_b64(hb + i * 8);
                const u64t h1 = lds_b64(hb + KHP * 4 + i * 8);
                const u64t h2 = lds_b64(hb + 2 * KHP * 4 + i * 8);
                const u64t h3 = lds_b64(hb + 3 * KHP * 4 + i * 8);
                const u64t wa = Wa[i], wb = Wb[i];
                fma2(A0, wa, h0); fma2(A1, wa, h1);
                fma2(A2, wa, h2); fma2(A3, wa, h3);
                fma2(B0, wb, h0); fma2(B1, wb, h1);
                fma2(B2, wb, h2); fma2(B3, wb, h3);
            }
            *reinterpret_cast<float4*>(&S.part[r0][c * 4]) =
                make_float4(hadd2(A0), hadd2(A1), hadd2(A2), hadd2(A3));
            *reinterpret_cast<float4*>(&S.part[r0 + 1][c * 4]) =
                make_float4(hadd2(B0), hadd2(B1), hadd2(B2), hadd2(B3));
        }
        __syncthreads();

        // ---- tail: reduce 8 chunks, gi, gates, DSMEM broadcast ----
        if (tid < KBPC * KU && jl_t < ucnt) {
            const int jl = jl_t, m = m_t;
            const float* pR = S.part[jl];
            const float* pZ = S.part[KU + jl];
            const float* pN = S.part[2 * KU + jl];
            float pr = 0.f, pz = 0.f, pn = 0.f;
            #pragma unroll
            for (int cc = 0; cc < NCH; ++cc) {
                pr += pR[cc * 4 + m];
                pz += pZ[cc * 4 + m];
                pn += pN[cc * 4 + m];
            }
            const float* xr = S.xs[t & 1][m];
            float gr = 0.f, gz = 0.f, gn = 0.f;
            #pragma unroll
            for (int f = 0; f < KF; ++f) {
                const float xf = xr[f];
                gr = fmaf(S.WihT[f][jl], xf, gr);
                gz = fmaf(S.WihT[f][KU + jl], xf, gz);
                gn = fmaf(S.WihT[f][2 * KU + jl], xf, gn);
            }
            const float r = sigm_fast(pr + gr + S.bsum[jl]);
            const float z = sigm_fast(pz + gz + S.bsum[KU + jl]);
            const float n = tanh_fast(gn + S.bihN[jl] + r * (pn + S.bhhN[jl]));
            const float hn = (1.0f - z) * n + z * S.h[p][m][u0 + jl];
            const uint32_t off = p ? offB : offA;
            st_cluster_f32(R0 + off, hn); st_cluster_f32(R1 + off, hn);
            st_cluster_f32(R2 + off, hn); st_cluster_f32(R3 + off, hn);
            st_cluster_f32(R4 + off, hn); st_cluster_f32(R5 + off, hn);
            st_cluster_f32(R6 + off, hn); st_cluster_f32(R7 + off, hn);
        }
        if (doPref) S.xs[(t + 1) & 1][pm][pf] = xv;
        cluster_sync();   // drains remote stores; all CTAs step together
        p ^= 1;
    }

    // =======================================================================
    // Fused fc + relu + decoder: ranks 0-3 handle batch m = rank.
    // Encoder h for this cluster is complete in local S.h[p].
    // =======================================================================
    if (rank < KBPC) {
        const int m = rank;
        const int b = cluster * KBPC + m;
        float* embS = &S.part[0][0];       // 300 floats (reuse part scratch)
        float* dgiS = embS + 304;          // 39 floats

        // emb = relu(h_last @ fc_W^T + fc_b)
        const float* hrow = &S.h[p][m][0];
        for (int j = tid; j < KH; j += KTHR) {
            const float4* wr = reinterpret_cast<const float4*>(fcW + (size_t)j * KH);
            float s0 = 0.f, s1 = 0.f, s2 = 0.f, s3 = 0.f;
            #pragma unroll 5
            for (int k = 0; k < KH / 4; ++k) {
                const float4 w4 = wr[k];
                const float4 h4 = *reinterpret_cast<const float4*>(&hrow[k * 4]);
                s0 = fmaf(w4.x, h4.x, s0); s1 = fmaf(w4.y, h4.y, s1);
                s2 = fmaf(w4.z, h4.z, s2); s3 = fmaf(w4.w, h4.w, s3);
            }
            float s = fcb[j] + ((s0 + s1) + (s2 + s3));
            s = fmaxf(s, 0.0f);
            embS[j] = s;
            if (writeEmb)
                out[(size_t)KB * KT * KF + (size_t)b * KH + j] = s;
        }
        __syncthreads();

        // dgi = emb @ dec_Wih^T + dec_bih (constant across decoder steps)
        if (tid < 3 * KF) {
            const float4* wr = reinterpret_cast<const float4*>(dWih + (size_t)tid * KH);
            float s0 = 0.f, s1 = 0.f, s2 = 0.f, s3 = 0.f;
            #pragma unroll 5
            for (int k = 0; k < KH / 4; ++k) {
                const float4 w4 = wr[k];
                const float4 h4 = *reinterpret_cast<const float4*>(&embS[k * 4]);
                s0 = fmaf(w4.x, h4.x, s0); s1 = fmaf(w4.y, h4.y, s1);
                s2 = fmaf(w4.z, h4.z, s2); s3 = fmaf(w4.w, h4.w, s3);
            }
            dgiS[tid] = dbih[tid] + ((s0 + s1) + (s2 + s3));
        }
        __syncthreads();

        // decoder loop: warp 0, shuffle-based (h lives in lanes 0-12)
        if (tid < 32) {
            const int lane = tid;
            const bool act = (lane < KF);
            float wr_[KF], wz_[KF], wn_[KF];
            #pragma unroll
            for (int k = 0; k < KF; ++k) {
                wr_[k] = act ? dWhh[(size_t)lane * KF + k]            : 0.f;
                wz_[k] = act ? dWhh[(size_t)(KF + lane) * KF + k]     : 0.f;
                wn_[k] = act ? dWhh[(size_t)(2 * KF + lane) * KF + k] : 0.f;
            }
            const float bhr = act ? dbhh[lane]          : 0.f;
            const float bhz = act ? dbhh[KF + lane]     : 0.f;
            const float bhn = act ? dbhh[2 * KF + lane] : 0.f;
            const float dgr = act ? dgiS[lane]          : 0.f;
            const float dgz = act ? dgiS[KF + lane]     : 0.f;
            const float dgn = act ? dgiS[2 * KF + lane] : 0.f;
            float hv = 0.f;
            float* op = out + (size_t)b * KT * KF;

            for (int t = 0; t < KT; ++t) {
                float sr = bhr, sz = bhz, sn = bhn;
                #pragma unroll
                for (int k = 0; k < KF; ++k) {
                    const float hk = __shfl_sync(0xffffffffu, hv, k);
                    sr = fmaf(wr_[k], hk, sr);
                    sz = fmaf(wz_[k], hk, sz);
                    sn = fmaf(wn_[k], hk, sn);
                }
                if (act) {
                    const float r = sigm_fast(dgr + sr);
                    const float z = sigm_fast(dgz + sz);
                    const float n = tanh_fast(dgn + r * sn);
                    hv = (1.0f - z) * n + z * hv;
                    op[(size_t)t * KF + lane] = hv;
                }
            }
        }
    }
}

extern "C" void kernel_launch(void* const* d_in, const int* in_sizes, int n_in,
                              void* d_out, int out_size)
{
    const float* x    = (const float*)d_in[0];
    const float* eWih = (const float*)d_in[1];
    const float* eWhh = (const float*)d_in[2];
    const float* ebih = (const float*)d_in[3];
    const float* ebhh = (const float*)d_in[4];
    const float* fcW  = (const float*)d_in[5];
    const float* fcb  = (const float*)d_in[6];
    const float* dWih = (const float*)d_in[7];
    const float* dWhh = (const float*)d_in[8];
    const float* dbih = (const float*)d_in[9];
    const float* dbhh = (const float*)d_in[10];
    float* out = (float*)d_out;

    const int writeEmb = (out_size >= KB * KT * KF + KB * KH) ? 1 : 0;

    enc_kernel<<<(KB / KBPC) * KCL, KTHR>>>(
        x, eWih, eWhh, ebih, ebhh, fcW, fcb, dWih, dWhh, dbih, dbhh,
        out, writeEmb);
}